// round 4
// baseline (speedup 1.0000x reference)
#include <cuda_runtime.h>

#define NN 20000
#define EE 640000
#define HH 128
#define EPS_BN   1e-5f
#define EPS_NORM 1e-6f

// ---------------- scratch (static __device__: allocation-free) ----------------
__device__ int   g_is64;
__device__ int   g_src32[EE];
__device__ int   g_dst32[EE];
__device__ int   g_deg[NN];
__device__ int   g_rowptr[NN + 1];
__device__ int   g_cursor[NN];
__device__ int   g_eidx[EE];
__device__ float g_A[NN * HH];   // nf @ Wg[:, 0:H].T   + bg
__device__ float g_B[NN * HH];   // nf @ Wg[:, H:2H].T
__device__ float g_D[NN * HH];   // nf @ Wd.T + bd
__device__ float g_S[NN * HH];   // nf @ Ws.T + bs
__device__ float g_h[NN * HH];   // pre-BN node update
__device__ float g_stats[4 * HH];   // [sumZ, sumsqZ, sumN, sumsqN]
__device__ float g_scale[4 * HH];   // [scaleZ, shiftZ, scaleN, shiftN]

__device__ __forceinline__ float fsigmoid(float x) { return 1.f / (1.f + __expf(-x)); }
__device__ __forceinline__ float fsilu(float x)    { return x / (1.f + __expf(-x)); }

// ---------------- dtype detection: int64 vs int32 edge_index ----------------
__global__ void k_detect(const int* __restrict__ p) {
    __shared__ int nz;
    if (threadIdx.x == 0) nz = 0;
    __syncthreads();
    int bad = 0;
    for (int i = threadIdx.x; i < 4096; i += blockDim.x)
        if (p[2 * i + 1] != 0) bad = 1;         // odd words all-zero <=> little-endian int64 of small values
    if (bad) atomicExch(&nz, 1);
    __syncthreads();
    if (threadIdx.x == 0) g_is64 = (nz == 0) ? 1 : 0;
}

__global__ void k_convert(const void* __restrict__ eiv) {
    int e = blockIdx.x * blockDim.x + threadIdx.x;
    if (e >= EE) return;
    if (g_is64) {
        const long long* p = (const long long*)eiv;
        g_src32[e] = (int)p[e];
        g_dst32[e] = (int)p[EE + e];
    } else {
        const int* p = (const int*)eiv;
        g_src32[e] = p[e];
        g_dst32[e] = p[EE + e];
    }
}

// ---------------- CSR build ----------------
__global__ void k_zero() {
    int i = blockIdx.x * blockDim.x + threadIdx.x;
    if (i < NN)  g_deg[i] = 0;
    if (i < 4 * HH) g_stats[i] = 0.f;
}

__global__ void k_hist() {
    int e = blockIdx.x * blockDim.x + threadIdx.x;
    if (e < EE) atomicAdd(&g_deg[g_src32[e]], 1);
}

__global__ void k_scan() {  // 1 block, 512 threads
    __shared__ int ssum[512];
    int t = threadIdx.x;
    const int CH = (NN + 511) / 512;   // 40
    int base = t * CH;
    int s = 0;
    for (int i = 0; i < CH; i++) {
        int idx = base + i;
        if (idx < NN) s += g_deg[idx];
    }
    ssum[t] = s;
    __syncthreads();
    for (int off = 1; off < 512; off <<= 1) {
        int v = (t >= off) ? ssum[t - off] : 0;
        __syncthreads();
        ssum[t] += v;
        __syncthreads();
    }
    int excl = (t == 0) ? 0 : ssum[t - 1];
    for (int i = 0; i < CH; i++) {
        int idx = base + i;
        if (idx < NN) {
            int d = g_deg[idx];
            g_rowptr[idx] = excl;
            g_cursor[idx] = excl;
            excl += d;
        }
    }
    if (t == 0) g_rowptr[NN] = ssum[511];
}

__global__ void k_scatter() {
    int e = blockIdx.x * blockDim.x + threadIdx.x;
    if (e >= EE) return;
    int p = atomicAdd(&g_cursor[g_src32[e]], 1);
    g_eidx[p] = e;
}

// ---------------- node GEMMs: A, B, D, S (blockIdx.y selects) ----------------
__global__ __launch_bounds__(256) void k_node_gemm(
    const float* __restrict__ nf,
    const float* __restrict__ Wg, const float* __restrict__ bg,
    const float* __restrict__ Wd, const float* __restrict__ bd,
    const float* __restrict__ Ws, const float* __restrict__ bs)
{
    const float* W; const float* bias; float* out; int wstride, woff;
    switch (blockIdx.y) {
        case 0:  W = Wg; wstride = 3 * HH; woff = 0;  bias = bg; out = g_A; break;
        case 1:  W = Wg; wstride = 3 * HH; woff = HH; bias = 0;  out = g_B; break;
        case 2:  W = Wd; wstride = HH;     woff = 0;  bias = bd; out = g_D; break;
        default: W = Ws; wstride = HH;     woff = 0;  bias = bs; out = g_S; break;
    }
    __shared__ float sX[16][HH + 4];
    __shared__ float sW[16][HH + 4];
    int tid = threadIdx.x, tx = tid & 15, ty = tid >> 4;
    int bn = blockIdx.x * 128;
    float acc[8][8] = {};

    for (int k0 = 0; k0 < HH; k0 += 16) {
        #pragma unroll
        for (int l = 0; l < 2; l++) {
            int i = tid + l * 256;
            int r = i >> 2, kq = (i & 3) * 4;
            int gn = bn + r;
            float4 v = make_float4(0.f, 0.f, 0.f, 0.f);
            if (gn < NN) v = *(const float4*)&nf[gn * HH + k0 + kq];
            sX[kq + 0][r] = v.x; sX[kq + 1][r] = v.y; sX[kq + 2][r] = v.z; sX[kq + 3][r] = v.w;
            float4 w = *(const float4*)&W[r * wstride + woff + k0 + kq];
            sW[kq + 0][r] = w.x; sW[kq + 1][r] = w.y; sW[kq + 2][r] = w.z; sW[kq + 3][r] = w.w;
        }
        __syncthreads();
        #pragma unroll
        for (int k = 0; k < 16; k++) {
            float4 a0 = *(const float4*)&sX[k][ty * 4];
            float4 a1 = *(const float4*)&sX[k][64 + ty * 4];
            float4 b0 = *(const float4*)&sW[k][tx * 4];
            float4 b1 = *(const float4*)&sW[k][64 + tx * 4];
            float a[8] = {a0.x, a0.y, a0.z, a0.w, a1.x, a1.y, a1.z, a1.w};
            float b[8] = {b0.x, b0.y, b0.z, b0.w, b1.x, b1.y, b1.z, b1.w};
            #pragma unroll
            for (int i = 0; i < 8; i++)
                #pragma unroll
                for (int j = 0; j < 8; j++)
                    acc[i][j] = fmaf(a[i], b[j], acc[i][j]);
        }
        __syncthreads();
    }
    #pragma unroll
    for (int ih = 0; ih < 2; ih++)
        #pragma unroll
        for (int ii = 0; ii < 4; ii++) {
            int m = ih * 64 + ty * 4 + ii;
            int gn = bn + m;
            if (gn >= NN) continue;
            #pragma unroll
            for (int jh = 0; jh < 2; jh++) {
                int h = jh * 64 + tx * 4;
                float4 o;
                o.x = acc[ih * 4 + ii][jh * 4 + 0];
                o.y = acc[ih * 4 + ii][jh * 4 + 1];
                o.z = acc[ih * 4 + ii][jh * 4 + 2];
                o.w = acc[ih * 4 + ii][jh * 4 + 3];
                if (bias) { o.x += bias[h]; o.y += bias[h + 1]; o.z += bias[h + 2]; o.w += bias[h + 3]; }
                *(float4*)&out[gn * HH + h] = o;
            }
        }
}

// ---------------- edge GEMM: lin[e] = ef[e] @ Wg3.T + A[src] + B[dst] ----------------
__global__ __launch_bounds__(256) void k_edge_gemm(
    const float* __restrict__ ef, const float* __restrict__ Wg,
    float* __restrict__ lin)
{
    __shared__ float sE[16][HH + 4];
    __shared__ float sW[16][HH + 4];
    __shared__ int sSrc[128], sDst[128];
    int tid = threadIdx.x, tx = tid & 15, ty = tid >> 4;
    int be = blockIdx.x * 128;
    if (tid < 128) { sSrc[tid] = g_src32[be + tid]; sDst[tid] = g_dst32[be + tid]; }
    float acc[8][8] = {};

    for (int k0 = 0; k0 < HH; k0 += 16) {
        #pragma unroll
        for (int l = 0; l < 2; l++) {
            int i = tid + l * 256;
            int r = i >> 2, kq = (i & 3) * 4;
            float4 v = *(const float4*)&ef[(be + r) * HH + k0 + kq];
            sE[kq + 0][r] = v.x; sE[kq + 1][r] = v.y; sE[kq + 2][r] = v.z; sE[kq + 3][r] = v.w;
            float4 w = *(const float4*)&Wg[r * (3 * HH) + 2 * HH + k0 + kq];
            sW[kq + 0][r] = w.x; sW[kq + 1][r] = w.y; sW[kq + 2][r] = w.z; sW[kq + 3][r] = w.w;
        }
        __syncthreads();
        #pragma unroll
        for (int k = 0; k < 16; k++) {
            float4 a0 = *(const float4*)&sE[k][ty * 4];
            float4 a1 = *(const float4*)&sE[k][64 + ty * 4];
            float4 b0 = *(const float4*)&sW[k][tx * 4];
            float4 b1 = *(const float4*)&sW[k][64 + tx * 4];
            float a[8] = {a0.x, a0.y, a0.z, a0.w, a1.x, a1.y, a1.z, a1.w};
            float b[8] = {b0.x, b0.y, b0.z, b0.w, b1.x, b1.y, b1.z, b1.w};
            #pragma unroll
            for (int i = 0; i < 8; i++)
                #pragma unroll
                for (int j = 0; j < 8; j++)
                    acc[i][j] = fmaf(a[i], b[j], acc[i][j]);
        }
        __syncthreads();
    }
    #pragma unroll
    for (int ih = 0; ih < 2; ih++)
        #pragma unroll
        for (int ii = 0; ii < 4; ii++) {
            int m = ih * 64 + ty * 4 + ii;
            int e = be + m;
            int s = sSrc[m], d = sDst[m];
            #pragma unroll
            for (int jh = 0; jh < 2; jh++) {
                int h = jh * 64 + tx * 4;
                float4 va = *(const float4*)&g_A[s * HH + h];
                float4 vb = *(const float4*)&g_B[d * HH + h];
                float4 o;
                o.x = acc[ih * 4 + ii][jh * 4 + 0] + va.x + vb.x;
                o.y = acc[ih * 4 + ii][jh * 4 + 1] + va.y + vb.y;
                o.z = acc[ih * 4 + ii][jh * 4 + 2] + va.z + vb.z;
                o.w = acc[ih * 4 + ii][jh * 4 + 3] + va.w + vb.w;
                *(float4*)&lin[e * HH + h] = o;
            }
        }
}

// ---------------- per-channel batch stats (sum, sumsq) ----------------
__global__ void k_stats(const float* __restrict__ xp, int rows, int statsOff, int useH) {
    const float* x = useH ? g_h : xp;
    int c = threadIdx.x;   // 0..127
    float s = 0.f, q = 0.f;
    for (int r = blockIdx.x; r < rows; r += gridDim.x) {
        float v = x[r * HH + c];
        s += v;
        q = fmaf(v, v, q);
    }
    atomicAdd(&g_stats[statsOff + c], s);
    atomicAdd(&g_stats[statsOff + HH + c], q);
}

__global__ void k_finalize(int statsOff, int outOff,
                           const float* __restrict__ gamma,
                           const float* __restrict__ beta, float cnt) {
    int c = threadIdx.x;
    float mean = g_stats[statsOff + c] / cnt;
    float var  = g_stats[statsOff + HH + c] / cnt - mean * mean;
    float sc   = gamma[c] * rsqrtf(var + EPS_BN);
    g_scale[outOff + c]      = sc;
    g_scale[outOff + HH + c] = beta[c] - mean * sc;
}

// ---------------- in-place: ue = silu(bn(lin)) over edge output region ----------------
__global__ void k_edge_bn(float* __restrict__ lin) {
    __shared__ float ssc[HH], ssh[HH];
    int t = threadIdx.x;
    if (t < HH) { ssc[t] = g_scale[t]; ssh[t] = g_scale[HH + t]; }
    __syncthreads();
    const int total = EE * (HH / 4);
    float4* p = (float4*)lin;
    for (int i = blockIdx.x * blockDim.x + t; i < total; i += gridDim.x * blockDim.x) {
        int cq = (i & 31) * 4;
        float4 v = p[i];
        v.x = fsilu(fmaf(v.x, ssc[cq + 0], ssh[cq + 0]));
        v.y = fsilu(fmaf(v.y, ssc[cq + 1], ssh[cq + 1]));
        v.z = fsilu(fmaf(v.z, ssc[cq + 2], ssh[cq + 2]));
        v.w = fsilu(fmaf(v.w, ssc[cq + 3], ssh[cq + 3]));
        p[i] = v;
    }
}

// ---------------- node-centric CSR pass: agg + weighted scatter, no atomics ----------------
__global__ __launch_bounds__(128) void k_nodepass(const float* __restrict__ ue) {
    int n = blockIdx.x;
    int c = threadIdx.x;
    int b0 = g_rowptr[n], b1 = g_rowptr[n + 1];
    float agg = 0.f;
    for (int i = b0; i < b1; i++) {
        int e = g_eidx[i];
        agg += fsigmoid(ue[e * HH + c]);
    }
    float inv = 1.f / (agg + EPS_NORM);
    float acc = 0.f;
    for (int i = b0; i < b1; i++) {
        int e = g_eidx[i];
        int d = g_dst32[e];
        float sg = fsigmoid(ue[e * HH + c]);
        acc = fmaf(sg, g_D[d * HH + c], acc);
    }
    g_h[n * HH + c] = g_S[n * HH + c] + acc * inv;
}

// ---------------- final node output: nf + silu(bn(h)) ----------------
__global__ void k_nodes_out(const float* __restrict__ nf, float* __restrict__ outN) {
    int i = blockIdx.x * blockDim.x + threadIdx.x;
    if (i >= NN * HH) return;
    int c = i & (HH - 1);
    float x = fmaf(g_h[i], g_scale[2 * HH + c], g_scale[3 * HH + c]);
    outN[i] = nf[i] + fsilu(x);
}

// ---------------- launch ----------------
extern "C" void kernel_launch(void* const* d_in, const int* in_sizes, int n_in,
                              void* d_out, int out_size) {
    const void*  ei = d_in[0];
    const float* nf = (const float*)d_in[1];
    const float* ef = (const float*)d_in[2];
    const float* Wg = (const float*)d_in[3];
    const float* bg = (const float*)d_in[4];
    const float* Ws = (const float*)d_in[5];
    const float* bs = (const float*)d_in[6];
    const float* Wd = (const float*)d_in[7];
    const float* bd = (const float*)d_in[8];
    const float* zg = (const float*)d_in[9];
    const float* zb = (const float*)d_in[10];
    const float* ng = (const float*)d_in[11];
    const float* nb = (const float*)d_in[12];

    float* outN = (float*)d_out;            // [N, H] updated_nodes
    float* lin  = outN + (size_t)NN * HH;   // [E, H] lin -> updated_edge (in place)

    k_detect<<<1, 256>>>((const int*)ei);
    k_convert<<<(EE + 255) / 256, 256>>>(ei);
    k_zero<<<(NN + 255) / 256, 256>>>();
    k_hist<<<(EE + 255) / 256, 256>>>();
    k_scan<<<1, 512>>>();
    k_scatter<<<(EE + 255) / 256, 256>>>();
    k_node_gemm<<<dim3((NN + 127) / 128, 4), 256>>>(nf, Wg, bg, Wd, bd, Ws, bs);
    k_edge_gemm<<<EE / 128, 256>>>(ef, Wg, lin);
    k_stats<<<2048, 128>>>(lin, EE, 0, 0);
    k_finalize<<<1, 128>>>(0, 0, zg, zb, (float)EE);
    k_edge_bn<<<2048, 256>>>(lin);
    k_nodepass<<<NN, 128>>>(lin);
    k_stats<<<2048, 128>>>(nullptr, NN, 2 * HH, 1);
    k_finalize<<<1, 128>>>(2 * HH, 2 * HH, ng, nb, (float)NN);
    k_nodes_out<<<(NN * HH + 255) / 256, 256>>>(nf, outN);
}